// round 10
// baseline (speedup 1.0000x reference)
#include <cuda_runtime.h>
#include <math.h>

#define T_SEQ 512
#define NB    64
#define NI    256
#define NH    512

// Per-batch-group barrier counters: MONOTONIC across graph replays, never
// reset. Each launch adds exactly 512*16 = 8192 arrivals per counter, so
// base = value & ~8191 is correct no matter when a CTA reads it.
__device__ unsigned g_barg[8 * 64];   // 8 counters, 256 B apart

typedef unsigned long long ull;

// Packed 2x fp32 FMA (sm_10x f32x2 pipe).
#define FFMA2(d, a, b, c) \
    asm("fma.rn.f32x2 %0, %1, %2, %3;" : "=l"(d) : "l"(a), "l"(b), "l"(c))

__device__ __forceinline__ float2 unpack2(ull v) {
    unsigned lo, hi;
    asm("mov.b64 {%0, %1}, %2;" : "=r"(lo), "=r"(hi) : "l"(v));
    return make_float2(__uint_as_float(lo), __uint_as_float(hi));
}

__device__ __forceinline__ unsigned smem_u32(const void* p) {
    return (unsigned)__cvta_generic_to_shared(p);
}
__device__ __forceinline__ void mbar_init(unsigned a, unsigned cnt) {
    asm volatile("mbarrier.init.shared.b64 [%0], %1;" :: "r"(a), "r"(cnt)
                 : "memory");
}
__device__ __forceinline__ void mbar_arrive(unsigned a) {
    asm volatile("mbarrier.arrive.shared.b64 _, [%0];" :: "r"(a) : "memory");
}
__device__ __forceinline__ void mbar_wait(unsigned a, unsigned parity) {
    unsigned done;
    do {
        asm volatile(
            "{\n\t.reg .pred p;\n\t"
            "mbarrier.try_wait.parity.shared.b64 p, [%1], %2, 0x989680;\n\t"
            "selp.b32 %0, 1, 0, p;\n\t}"
            : "=r"(done) : "r"(a), "r"(parity) : "memory");
    } while (!done);
}

// ---- dynamic smem layout (float indices) ----------------------------------
#define HS_OFF    0        // h tile [8][512]                   (16 KB)
#define PART_OFF  4096     // partials [8 ks][8 b][32 lane]     ( 8 KB)
#define RING_OFF  6144     // pre ring [2 slot][8 b][32 j]      ( 2 KB)
#define XB_OFF    6656     // x rows [8 b][256]                 ( 8 KB)
#define WT_OFF    8704     // W_ih^T packed [64 k4][32 j][4]    (32 KB)
#define MBAR_OFF  16896    // 4 mbarriers (full0, full1, e0, e1) + base word
#define SM_FLOATS 16912

#define RT 384   // warps 0..7 consumers (256 thr), 8..11 producers

__global__ __launch_bounds__(RT, 1) void rnn_fused(
    const float* __restrict__ x,     // [T][B][I]
    const float* __restrict__ h0,    // [B][H]
    const float* __restrict__ Wih,   // [H][I]
    const float* __restrict__ Whh,   // [H][H]
    const float* __restrict__ bih,   // [H]
    const float* __restrict__ bhh,   // [H]
    float* __restrict__ hseq,        // [T][B][H]
    float* __restrict__ hlast)       // [B][H] or nullptr
{
    extern __shared__ float sm[];

    const int tid  = threadIdx.x;
    const int lane = tid & 31;
    const int warp = tid >> 5;
    const int jt   = blockIdx.x & 15;
    const int bt   = blockIdx.x >> 4;
    const int j0   = jt * 32;
    const int b0   = bt * 8;
    unsigned* const bar = &g_barg[bt * 64];

    const unsigned a_full0  = smem_u32(sm + MBAR_OFF);       // +0, +8
    const unsigned a_empty0 = smem_u32(sm + MBAR_OFF + 4);   // +0, +8
    unsigned* const pbase   = (unsigned*)(sm + MBAR_OFF + 8);

    if (tid == 0) {
        mbar_init(a_full0,      4);   // 4 producer warps
        mbar_init(a_full0  + 8, 4);
        mbar_init(a_empty0,     8);   // 8 consumer warps
        mbar_init(a_empty0 + 8, 8);
        *pbase = (*(volatile unsigned*)bar) & ~8191u;
    }
    // Producers stage W_ih^T packed: Wt4[k>>2][j][k&3].
    if (warp >= 8) {
        const int ptid = tid - 256;   // 0..127
        for (int e = ptid; e < 32 * NI; e += 128) {
            int jj = e >> 8;
            int k  = e & 255;
            sm[WT_OFF + (k >> 2) * 128 + jj * 4 + (k & 3)] =
                Wih[(size_t)(j0 + jj) * NI + k];
        }
    }
    __syncthreads();
    const unsigned base = *pbase;

    if (warp < 8) {
        // ================= CONSUMER (recurrence) =================
        const int ks = warp;          // k-slice this warp computes
        const int k0 = ks * 64;
        const int j  = j0 + lane;     // column owned for W / reduce output

        // W_hh[j][k0..k0+63] -> 32 packed-pair registers.
        ull w2[32];
        {
            const ulonglong2* wp =
                (const ulonglong2*)(Whh + (size_t)j * NH + k0);
#pragma unroll
            for (int c = 0; c < 16; ++c) {
                ulonglong2 v = __ldg(wp + c);
                w2[2 * c]     = v.x;
                w2[2 * c + 1] = v.y;
            }
        }

        unsigned pf0 = 0, pf1 = 0;    // full-ring parities per slot

        for (int t = 0; t < T_SEQ; ++t) {
            const int slot = t & 1;
            // Wait for pre[t] tile (producers are normally 2 steps ahead).
            if (slot) { mbar_wait(a_full0 + 8, pf1); pf1 ^= 1; }
            else      { mbar_wait(a_full0,     pf0); pf0 ^= 1; }

            // Stage OWN h slice (8 batches x 64 cols) — warp-private.
            const float* hprev =
                t ? hseq + (size_t)(t - 1) * NB * NH : h0;
#pragma unroll
            for (int i = 0; i < 4; ++i) {
                int idx = lane + 32 * i;       // 0..127
                int row = idx >> 4;
                int c4  = idx & 15;
                float4 v = __ldcg((const float4*)(hprev +
                              (size_t)(b0 + row) * NH + k0 + c4 * 4));
                *(float4*)(sm + HS_OFF + row * NH + k0 + c4 * 4) = v;
            }
            __syncwarp();

            // 8 partial dots (one per batch), K-slice 64, packed FMAs.
            float accs[8];
#pragma unroll
            for (int b = 0; b < 8; ++b) {
                const ulonglong2* hp =
                    (const ulonglong2*)(sm + HS_OFF + b * NH + k0);
                ull a0 = 0ull, a1 = 0ull;
#pragma unroll
                for (int c = 0; c < 16; ++c) {
                    ulonglong2 hv = hp[c];   // broadcast LDS.128
                    FFMA2(a0, w2[2 * c],     hv.x, a0);
                    FFMA2(a1, w2[2 * c + 1], hv.y, a1);
                }
                float2 f0 = unpack2(a0);
                float2 f1 = unpack2(a1);
                accs[b] = (f0.x + f0.y) + (f1.x + f1.y);
            }
#pragma unroll
            for (int b = 0; b < 8; ++b)
                sm[PART_OFF + ks * 256 + b * 32 + lane] = accs[b];
            asm volatile("bar.sync 1, 256;" ::: "memory");

            // Reduce role: this warp = batch `warp`, column j0+lane.
            float s = 0.f;
#pragma unroll
            for (int w = 0; w < 8; ++w)
                s += sm[PART_OFF + w * 256 + warp * 32 + lane];
            const float pre = sm[RING_OFF + slot * 256 + warp * 32 + lane];
            const float hv  = tanhf(s + pre);
            const int   bo  = b0 + warp;
            hseq[((size_t)t * NB + bo) * NH + j0 + lane] = hv;
            if (t == T_SEQ - 1 && hlast)
                hlast[(size_t)bo * NH + j0 + lane] = hv;

            // Ring slot consumed -> let producers reuse it.
            __syncwarp();
            if (lane == 0) mbar_arrive(a_empty0 + (unsigned)slot * 8);

            asm volatile("bar.sync 1, 256;" ::: "memory");
            // Group barrier: 16 CTAs sharing bt. Final step: arrive only.
            if (tid == 0) {
                asm volatile("red.release.gpu.global.add.u32 [%0], 1;"
                             :: "l"(bar) : "memory");
                if (t != T_SEQ - 1) {
                    const unsigned target = base + (unsigned)(t + 1) * 16u;
                    unsigned f;
                    do {
                        asm volatile("ld.acquire.gpu.u32 %0, [%1];"
                                     : "=r"(f) : "l"(bar) : "memory");
                    } while (f < target);
                }
            }
            if (t != T_SEQ - 1)
                asm volatile("bar.sync 1, 256;" ::: "memory");
        }
    } else {
        // ================= PRODUCER (input projection) =================
        const int pw = warp - 8;      // 0..3, handles batches 2pw, 2pw+1
        const float bias = __ldg(bih + j0 + lane) + __ldg(bhh + j0 + lane);
        unsigned pe0 = 0, pe1 = 0;

        for (int t = 0; t < T_SEQ; ++t) {
            const int slot = t & 1;
            if (t >= 2) {   // wait until consumers finished step t-2's tile
                if (slot) { mbar_wait(a_empty0 + 8, pe1); pe1 ^= 1; }
                else      { mbar_wait(a_empty0,     pe0); pe0 ^= 1; }
            }

            // Stage x rows (2 batches x 256 floats) into warp-private smem.
#pragma unroll
            for (int r = 0; r < 2; ++r) {
                const int b = pw * 2 + r;
#pragma unroll
                for (int i = 0; i < 2; ++i) {
                    int c4 = lane + 32 * i;    // 0..63
                    float4 v = __ldg((const float4*)(x +
                                 ((size_t)t * NB + b0 + b) * NI + c4 * 4));
                    *(float4*)(sm + XB_OFF + b * NI + c4 * 4) = v;
                }
            }
            __syncwarp();

            // pre[b][j0+lane] = dot(x[b], Wih[j0+lane]) + bias.
#pragma unroll
            for (int r = 0; r < 2; ++r) {
                const int b = pw * 2 + r;
                const ulonglong2* xp =
                    (const ulonglong2*)(sm + XB_OFF + b * NI);
                const ulonglong2* wp = (const ulonglong2*)(sm + WT_OFF);
                ull a0 = 0ull, a1 = 0ull;
#pragma unroll 8
                for (int k4 = 0; k4 < 64; ++k4) {
                    ulonglong2 xv = xp[k4];             // uniform (broadcast)
                    ulonglong2 wv = wp[k4 * 32 + lane]; // per-lane row
                    FFMA2(a0, wv.x, xv.x, a0);
                    FFMA2(a1, wv.y, xv.y, a1);
                }
                float2 f0 = unpack2(a0);
                float2 f1 = unpack2(a1);
                sm[RING_OFF + slot * 256 + b * 32 + lane] =
                    (f0.x + f0.y) + (f1.x + f1.y) + bias;
            }
            __syncwarp();
            if (lane == 0) mbar_arrive(a_full0 + (unsigned)slot * 8);
        }
    }
}

// ---------------------------------------------------------------------------
extern "C" void kernel_launch(void* const* d_in, const int* in_sizes, int n_in,
                              void* d_out, int out_size)
{
    const float* x   = (const float*)d_in[0];
    const float* h0  = (const float*)d_in[1];
    const float* Wih = (const float*)d_in[2];
    const float* Whh = (const float*)d_in[3];
    const float* bih = (const float*)d_in[4];
    const float* bhh = (const float*)d_in[5];
    float* out = (float*)d_out;

    float* hlast = nullptr;
    if (out_size >= (int)((size_t)T_SEQ * NB * NH + NB * NH))
        hlast = out + (size_t)T_SEQ * NB * NH;

    const size_t smem = SM_FLOATS * sizeof(float);   // 67648 B
    cudaFuncSetAttribute(rnn_fused,
                         cudaFuncAttributeMaxDynamicSharedMemorySize,
                         (int)smem);
    rnn_fused<<<128, RT, smem>>>(x, h0, Wih, Whh, bih, bhh, out, hlast);
}

// round 11
// speedup vs baseline: 1.2030x; 1.2030x over previous
#include <cuda_runtime.h>
#include <math.h>

#define T_SEQ 512
#define NB    64
#define NI    256
#define NH    512

// Per-batch-group barrier counters: MONOTONIC across graph replays, never
// reset. Each launch adds exactly 512*16 = 8192 arrivals per counter, so
// base = value & ~8191 read before this CTA's first arrival is correct.
__device__ unsigned g_barg[8 * 64];   // 8 counters, 256 B apart

typedef unsigned long long ull;

// Packed 2x fp32 FMA (sm_10x f32x2 pipe).
#define FFMA2(d, a, b, c) \
    asm("fma.rn.f32x2 %0, %1, %2, %3;" : "=l"(d) : "l"(a), "l"(b), "l"(c))

__device__ __forceinline__ float2 unpack2(ull v) {
    unsigned lo, hi;
    asm("mov.b64 {%0, %1}, %2;" : "=r"(lo), "=r"(hi) : "l"(v));
    return make_float2(__uint_as_float(lo), __uint_as_float(hi));
}

__device__ __forceinline__ unsigned smem_u32(const void* p) {
    return (unsigned)__cvta_generic_to_shared(p);
}
__device__ __forceinline__ void mbar_init(unsigned a, unsigned cnt) {
    asm volatile("mbarrier.init.shared.b64 [%0], %1;" :: "r"(a), "r"(cnt)
                 : "memory");
}
__device__ __forceinline__ void mbar_arrive(unsigned a) {
    asm volatile("mbarrier.arrive.release.cta.shared.b64 _, [%0];"
                 :: "r"(a) : "memory");
}
__device__ __forceinline__ void mbar_wait(unsigned a, unsigned parity) {
    unsigned done;
    do {
        asm volatile(
            "{\n\t.reg .pred p;\n\t"
            "mbarrier.try_wait.parity.acquire.cta.shared.b64 p, [%1], %2, 0x989680;\n\t"
            "selp.b32 %0, 1, 0, p;\n\t}"
            : "=r"(done) : "r"(a), "r"(parity) : "memory");
    } while (!done);
}

// ---- dynamic smem layout (float indices) ----------------------------------
#define HS_OFF    0       // h tile [8 b][512]                  (16 KB)
#define PART_OFF  4096    // consumer partials [8 ks][8 b][32]  ( 8 KB)
#define RING_OFF  6144    // pre ring [2 slot][8 b][32 j]       ( 2 KB)
#define XB_OFF    6656    // x tile [8 b][256]                  ( 8 KB)
#define PP_OFF    8704    // producer partials [4 pw][8 b][32]  ( 4 KB)
#define MBAR_OFF  9728    // full0, full1, empty0, empty1 (4x u64) + base
#define SM_FLOATS 9744

#define RT 384   // warps 0..7 consumers (256 thr), warps 8..11 producers

__global__ __launch_bounds__(RT, 1) void rnn_fused(
    const float* __restrict__ x,     // [T][B][I]
    const float* __restrict__ h0,    // [B][H]
    const float* __restrict__ Wih,   // [H][I]
    const float* __restrict__ Whh,   // [H][H]
    const float* __restrict__ bih,   // [H]
    const float* __restrict__ bhh,   // [H]
    float* __restrict__ hseq,        // [T][B][H]
    float* __restrict__ hlast)       // [B][H] or nullptr
{
    extern __shared__ float sm[];

    const int tid  = threadIdx.x;
    const int lane = tid & 31;
    const int warp = tid >> 5;
    const int jt   = blockIdx.x & 15;
    const int bt   = blockIdx.x >> 4;
    const int j0   = jt * 32;
    const int b0   = bt * 8;
    unsigned* const bar = &g_barg[bt * 64];

    const unsigned a_full0  = smem_u32(sm + MBAR_OFF);       // +0 / +8
    const unsigned a_empty0 = smem_u32(sm + MBAR_OFF + 4);   // +0 / +8
    unsigned* const pbase   = (unsigned*)(sm + MBAR_OFF + 8);

    if (tid == 0) {
        mbar_init(a_full0,      4);   // 4 producer warps arrive
        mbar_init(a_full0  + 8, 4);
        mbar_init(a_empty0,     8);   // 8 consumer warps arrive
        mbar_init(a_empty0 + 8, 8);
        *pbase = (*(volatile unsigned*)bar) & ~8191u;
    }
    __syncthreads();
    const unsigned base = *pbase;

    if (warp < 8) {
        // ================= CONSUMER (recurrence) =================
        const int ks = warp;          // k-slice this warp computes
        const int k0 = ks * 64;

        // W_hh[j0+lane][k0..k0+63] -> 32 packed-pair registers.
        ull w2[32];
        {
            const ulonglong2* wp =
                (const ulonglong2*)(Whh + (size_t)(j0 + lane) * NH + k0);
#pragma unroll
            for (int c = 0; c < 16; ++c) {
                ulonglong2 v = __ldg(wp + c);
                w2[2 * c]     = v.x;
                w2[2 * c + 1] = v.y;
            }
        }

        unsigned pf0 = 0, pf1 = 0;    // full-ring parities per slot

        for (int t = 0; t < T_SEQ; ++t) {
            const int slot = t & 1;

            // Stage OWN h slice (8 batches x 64 cols) — warp-private.
            const float* hprev = t ? hseq + (size_t)(t - 1) * NB * NH : h0;
#pragma unroll
            for (int i = 0; i < 4; ++i) {
                int idx = lane + 32 * i;       // 0..127 float4 slots
                int row = idx >> 4;
                int c4  = idx & 15;
                float4 v = __ldcg((const float4*)(hprev +
                              (size_t)(b0 + row) * NH + k0 + c4 * 4));
                *(float4*)(sm + HS_OFF + row * NH + k0 + c4 * 4) = v;
            }
            __syncwarp();

            // 8 partial dots (one per batch), K-slice 64, packed FMAs.
            float accs[8];
#pragma unroll
            for (int b = 0; b < 8; ++b) {
                const ulonglong2* hp =
                    (const ulonglong2*)(sm + HS_OFF + b * NH + k0);
                ull a0 = 0ull, a1 = 0ull;
#pragma unroll
                for (int c = 0; c < 16; ++c) {
                    ulonglong2 hv = hp[c];   // broadcast LDS.128 (1 phase)
                    FFMA2(a0, w2[2 * c],     hv.x, a0);
                    FFMA2(a1, w2[2 * c + 1], hv.y, a1);
                }
                float2 f0 = unpack2(a0);
                float2 f1 = unpack2(a1);
                accs[b] = (f0.x + f0.y) + (f1.x + f1.y);
            }
#pragma unroll
            for (int b = 0; b < 8; ++b)
                sm[PART_OFF + ks * 256 + b * 32 + lane] = accs[b];
            asm volatile("bar.sync 1, 256;" ::: "memory");

            // Reduce role: warp = batch, lane = column j0+lane.
            float s = 0.f;
#pragma unroll
            for (int w = 0; w < 8; ++w)
                s += sm[PART_OFF + w * 256 + warp * 32 + lane];

            // pre[t] ring read (producers had a full step of slack).
            if (slot) { mbar_wait(a_full0 + 8, pf1); pf1 ^= 1; }
            else      { mbar_wait(a_full0,     pf0); pf0 ^= 1; }
            const float pre = sm[RING_OFF + slot * 256 + warp * 32 + lane];

            const float hv = tanhf(s + pre);
            const int   bo = b0 + warp;
            hseq[((size_t)t * NB + bo) * NH + j0 + lane] = hv;
            if (t == T_SEQ - 1 && hlast)
                hlast[(size_t)bo * NH + j0 + lane] = hv;

            // Ring slot consumed -> producers may refill it.
            __syncwarp();
            if (lane == 0) mbar_arrive(a_empty0 + (unsigned)slot * 8);

            asm volatile("bar.sync 1, 256;" ::: "memory");
            // Group barrier: 16 CTAs sharing bt. Final step: arrive only.
            if (tid == 0) {
                asm volatile("red.release.gpu.global.add.u32 [%0], 1;"
                             :: "l"(bar) : "memory");
                if (t != T_SEQ - 1) {
                    const unsigned target = base + (unsigned)(t + 1) * 16u;
                    unsigned f;
                    do {
                        asm volatile("ld.acquire.gpu.u32 %0, [%1];"
                                     : "=r"(f) : "l"(bar) : "memory");
                    } while (f < target);
                }
            }
            if (t != T_SEQ - 1)
                asm volatile("bar.sync 1, 256;" ::: "memory");
        }
    } else {
        // ============ PRODUCER (input projection, smem-lean) ============
        const int pw   = warp - 8;    // 0..3
        const int k0   = pw * 64;     // producer k-slice of NI
        const int ptid = tid - 256;   // 0..127

        // W_ih[j0+lane][k0..k0+63] -> 32 packed-pair registers.
        ull wi2[32];
        {
            const ulonglong2* wp =
                (const ulonglong2*)(Wih + (size_t)(j0 + lane) * NI + k0);
#pragma unroll
            for (int c = 0; c < 16; ++c) {
                ulonglong2 v = __ldg(wp + c);
                wi2[2 * c]     = v.x;
                wi2[2 * c + 1] = v.y;
            }
        }
        const float bias = __ldg(bih + j0 + lane) + __ldg(bhh + j0 + lane);
        unsigned pe0 = 0, pe1 = 0;

        for (int t = 0; t < T_SEQ; ++t) {
            const int slot = t & 1;

            // Stage x tile (8 batches x 256) — 128 threads x 4 float4.
#pragma unroll
            for (int i = 0; i < 4; ++i) {
                int idx = ptid + 128 * i;      // 0..511 float4 slots
                int row = idx >> 6;
                int c4  = idx & 63;
                float4 v = __ldg((const float4*)(x +
                              ((size_t)t * NB + b0 + row) * NI + c4 * 4));
                *(float4*)(sm + XB_OFF + row * NI + c4 * 4) = v;
            }
            asm volatile("bar.sync 2, 128;" ::: "memory");

            // 8 partial dots over this warp's 64-k slice (broadcast LDS).
            float pacc[8];
#pragma unroll
            for (int b = 0; b < 8; ++b) {
                const ulonglong2* xp =
                    (const ulonglong2*)(sm + XB_OFF + b * NI + k0);
                ull a0 = 0ull, a1 = 0ull;
#pragma unroll
                for (int c = 0; c < 16; ++c) {
                    ulonglong2 xv = xp[c];   // broadcast LDS.128 (1 phase)
                    FFMA2(a0, wi2[2 * c],     xv.x, a0);
                    FFMA2(a1, wi2[2 * c + 1], xv.y, a1);
                }
                float2 f0 = unpack2(a0);
                float2 f1 = unpack2(a1);
                pacc[b] = (f0.x + f0.y) + (f1.x + f1.y);
            }
#pragma unroll
            for (int b = 0; b < 8; ++b)
                sm[PP_OFF + pw * 256 + b * 32 + lane] = pacc[b];
            asm volatile("bar.sync 2, 128;" ::: "memory");

            // Wait for ring slot to be free (consumers of step t-2 done).
            if (t >= 2) {
                if (slot) { mbar_wait(a_empty0 + 8, pe1); pe1 ^= 1; }
                else      { mbar_wait(a_empty0,     pe0); pe0 ^= 1; }
            }

            // Reduce: warp pw emits batches 2pw and 2pw+1.
#pragma unroll
            for (int r = 0; r < 2; ++r) {
                const int b = pw * 2 + r;
                float s = bias;
#pragma unroll
                for (int w = 0; w < 4; ++w)
                    s += sm[PP_OFF + w * 256 + b * 32 + lane];
                sm[RING_OFF + slot * 256 + b * 32 + lane] = s;
            }
            __syncwarp();
            if (lane == 0) mbar_arrive(a_full0 + (unsigned)slot * 8);
        }
    }
}

// ---------------------------------------------------------------------------
extern "C" void kernel_launch(void* const* d_in, const int* in_sizes, int n_in,
                              void* d_out, int out_size)
{
    const float* x   = (const float*)d_in[0];
    const float* h0  = (const float*)d_in[1];
    const float* Wih = (const float*)d_in[2];
    const float* Whh = (const float*)d_in[3];
    const float* bih = (const float*)d_in[4];
    const float* bhh = (const float*)d_in[5];
    float* out = (float*)d_out;

    float* hlast = nullptr;
    if (out_size >= (int)((size_t)T_SEQ * NB * NH + NB * NH))
        hlast = out + (size_t)T_SEQ * NB * NH;

    const size_t smem = SM_FLOATS * sizeof(float);   // 38976 B
    cudaFuncSetAttribute(rnn_fused,
                         cudaFuncAttributeMaxDynamicSharedMemorySize,
                         (int)smem);
    rnn_fused<<<128, RT, smem>>>(x, h0, Wih, Whh, bih, bhh, out, hlast);
}